// round 6
// baseline (speedup 1.0000x reference)
#include <cuda_runtime.h>
#include <math.h>

#define BB 64
#define TT 512
#define II 256
#define HH 512
#define CC 128

// Scratch (static device allocations are allowed; cudaMalloc is not)
__device__ float g_gates[(size_t)TT * BB * 4 * HH];   // [t][b][4H]  256 MB
__device__ float g_hs[(size_t)TT * BB * HH];          // [t][b][H]    64 MB
__device__ float g_h[2][BB * HH];                     // ping-pong h state

// Per-batch-group barrier state (4 groups x 32 CTAs), padded to own lines.
struct GBar { unsigned int count; unsigned int pad0[31];
              unsigned int gen;   unsigned int pad1[31]; };
__device__ GBar g_bars[4];

__device__ __forceinline__ float sigmoidf_(float x) {
    return 1.0f / (1.0f + expf(-x));
}

// Packed dual-FMA: acc(lo,hi) += a(lo,hi) * b(lo,hi)   (ptxas never auto-fuses)
__device__ __forceinline__ void ffma2(unsigned long long& acc,
                                      unsigned long long a,
                                      unsigned long long b) {
    asm("fma.rn.f32x2 %0, %1, %2, %0;" : "+l"(acc) : "l"(a), "l"(b));
}

__device__ __forceinline__ unsigned long long pack2(float x) {
    unsigned long long r;
    asm("mov.b64 %0, {%1, %1};" : "=l"(r) : "f"(x));
    return r;
}

__device__ __forceinline__ float pairsum(unsigned long long v) {
    float2 f = *(float2*)&v;
    return f.x + f.y;
}

// ---------------------------------------------------------------------------
// Phase 1: G[t][b][n] = x[b][t][:] . W_ih[n][:] + b_ih[n] + b_hh[n]
// 128x128 tile, BK=8, 256 threads, 8x8 per thread; inner loop in fma.rn.f32x2.
// ---------------------------------------------------------------------------
__global__ void __launch_bounds__(256) gates_gemm(
    const float* __restrict__ x,
    const float* __restrict__ W_ih,
    const float* __restrict__ b_ih,
    const float* __restrict__ b_hh)
{
    __shared__ float As[8][128];
    __shared__ float Bs[8][128];

    const int n0 = blockIdx.x * 128;
    const int m0 = blockIdx.y * 128;
    const int tid = threadIdx.x;
    const int tx = tid & 15;
    const int ty = tid >> 4;

    unsigned long long acc2[8][4];
#pragma unroll
    for (int i = 0; i < 8; i++)
#pragma unroll
        for (int j = 0; j < 4; j++) acc2[i][j] = 0ull;

    const int lr = tid >> 1;
    const int lk = (tid & 1) * 4;

    for (int k0 = 0; k0 < II; k0 += 8) {
        {
            float4 v = *(const float4*)(x + (size_t)(m0 + lr) * II + k0 + lk);
            As[lk + 0][lr] = v.x; As[lk + 1][lr] = v.y;
            As[lk + 2][lr] = v.z; As[lk + 3][lr] = v.w;
        }
        {
            float4 v = *(const float4*)(W_ih + (size_t)(n0 + lr) * II + k0 + lk);
            Bs[lk + 0][lr] = v.x; Bs[lk + 1][lr] = v.y;
            Bs[lk + 2][lr] = v.z; Bs[lk + 3][lr] = v.w;
        }
        __syncthreads();
#pragma unroll
        for (int k = 0; k < 8; k++) {
            float a[8];
            float4 a0 = *(const float4*)&As[k][ty * 4];
            float4 a1 = *(const float4*)&As[k][64 + ty * 4];
            ulonglong2 bp0 = *(const ulonglong2*)&Bs[k][tx * 4];
            ulonglong2 bp1 = *(const ulonglong2*)&Bs[k][64 + tx * 4];
            a[0]=a0.x; a[1]=a0.y; a[2]=a0.z; a[3]=a0.w;
            a[4]=a1.x; a[5]=a1.y; a[6]=a1.z; a[7]=a1.w;
#pragma unroll
            for (int i = 0; i < 8; i++) {
                unsigned long long a2 = pack2(a[i]);
                ffma2(acc2[i][0], a2, bp0.x);
                ffma2(acc2[i][1], a2, bp0.y);
                ffma2(acc2[i][2], a2, bp1.x);
                ffma2(acc2[i][3], a2, bp1.y);
            }
        }
        __syncthreads();
    }

#pragma unroll
    for (int i = 0; i < 8; i++) {
        int m = m0 + (i >> 2) * 64 + ty * 4 + (i & 3);
        int bb = m >> 9;
        int tt = m & 511;
        size_t row = ((size_t)tt * BB + bb) * (4 * HH);
#pragma unroll
        for (int j2 = 0; j2 < 4; j2++) {
            float2 f = *(float2*)&acc2[i][j2];
            int jlo = j2 * 2;
            int n0c = n0 + (jlo >> 2) * 64 + tx * 4 + (jlo & 3);
            g_gates[row + n0c]     = f.x + b_ih[n0c]     + b_hh[n0c];
            g_gates[row + n0c + 1] = f.y + b_ih[n0c + 1] + b_hh[n0c + 1];
        }
    }
}

// ---------------------------------------------------------------------------
// Phase 2: persistent recurrence, 2-D sharded, 2 cells/thread.
// Grid = 128 CTAs: blockIdx -> (bg 0..3, jg 0..31). CTA owns batches
// bg*16..+15 and units jg*16..+15. 128 threads: thread = (jl 0..15, blp 0..7)
// handles cells (b0+blp, j) and (b0+blp+8, j) -> the two cells SHARE the W
// registers, halving LDS per FMA. Weights stored gate-major
// ((g*16+u)*129 float4 pitch) -> conflict-free W and h LDS.
// Batch groups are fully independent -> 4 independent 32-CTA barriers.
// ---------------------------------------------------------------------------
#define W_PITCH 129                 // float4 units per weight row (pad vs 128)
#define H_PITCH 516                 // floats per staged h row (129 float4)
#define WSM_F4  (64 * W_PITCH)      // 64 weight rows (16 units x 4 gates)
#define SMEM_RECUR ((WSM_F4 * 16) + (16 * H_PITCH * 4))   // bytes

__global__ void __launch_bounds__(128) lstm_recur(const float* __restrict__ W_hh)
{
    extern __shared__ float smem[];
    float4* Ws4 = (float4*)smem;                      // [(g*16+u)*W_PITCH + k4]
    float*  hsm = smem + WSM_F4 * 4;                  // [bl*H_PITCH + k]

    const int tid = threadIdx.x;
    const int blp = tid & 7;           // 0..7
    const int jl  = tid >> 3;          // 0..15
    const int bg  = blockIdx.x & 3;
    const int jg  = blockIdx.x >> 2;
    const int b0  = bg * 16 + blp;
    const int b1  = b0 + 8;
    const int j   = jg * 16 + jl;
    const int j0  = jg * 16;

    // Load W_hh slice: 64 rows (g*16+u) x 128 float4.
    for (int idx = tid; idx < 64 * 128; idx += 128) {
        int r  = idx >> 7;             // 0..63 = g*16 + u
        int k4 = idx & 127;
        int g  = r >> 4;
        int u  = r & 15;
        Ws4[r * W_PITCH + k4] =
            *(const float4*)(W_hh + ((size_t)(g * HH + j0 + u)) * HH + k4 * 4);
    }

    // init read-buffer h to 0 (fresh every launch / graph replay)
    __stcg(&g_h[0][b0 * HH + j], 0.0f);
    __stcg(&g_h[0][b1 * HH + j], 0.0f);
    float c0 = 0.0f, c1 = 0.0f;

    // initial group barrier (also orders smem W loads via its syncthreads)
    {
        __threadfence();
        __syncthreads();
        if (tid == 0) {
            unsigned int my = *((volatile unsigned int*)&g_bars[bg].gen);
            unsigned int arrived = atomicAdd(&g_bars[bg].count, 1u);
            if (arrived == 31u) {
                atomicExch(&g_bars[bg].count, 0u);
                __threadfence();
                atomicAdd(&g_bars[bg].gen, 1u);
            } else {
                while (*((volatile unsigned int*)&g_bars[bg].gen) == my) { __nanosleep(32); }
            }
            __threadfence();
        }
        __syncthreads();
    }

    const ulonglong2* Wi = (const ulonglong2*)(Ws4 + ( 0 + jl) * W_PITCH);
    const ulonglong2* Wf = (const ulonglong2*)(Ws4 + (16 + jl) * W_PITCH);
    const ulonglong2* Wg = (const ulonglong2*)(Ws4 + (32 + jl) * W_PITCH);
    const ulonglong2* Wo = (const ulonglong2*)(Ws4 + (48 + jl) * W_PITCH);
    const ulonglong2* Hr0 = (const ulonglong2*)(hsm + blp * H_PITCH);
    const ulonglong2* Hr1 = (const ulonglong2*)(hsm + (blp + 8) * H_PITCH);

    for (int t = 0; t < TT; t++) {
        // Stage h[t] for this CTA's 16 batches into smem.
        const float* hsrc = &g_h[t & 1][(bg * 16) * HH];
#pragma unroll
        for (int i = 0; i < 16; i++) {
            float4 v = __ldcg((const float4*)(hsrc + (size_t)i * HH) + tid);
            *(float4*)(hsm + i * H_PITCH + tid * 4) = v;
        }

        // Prefetch precomputed gate inputs for both cells (DRAM; latency
        // hidden by the dot-product loop).
        const float* xg0 = &g_gates[((size_t)t * BB + b0) * (4 * HH) + j];
        const float* xg1 = &g_gates[((size_t)t * BB + b1) * (4 * HH) + j];
        float xi0 = __ldcg(xg0);            float xi1 = __ldcg(xg1);
        float xf0 = __ldcg(xg0 + HH);       float xf1 = __ldcg(xg1 + HH);
        float xg0g = __ldcg(xg0 + 2 * HH);  float xg1g = __ldcg(xg1 + 2 * HH);
        float xo0 = __ldcg(xg0 + 3 * HH);   float xo1 = __ldcg(xg1 + 3 * HH);

        __syncthreads();   // staged h visible

        unsigned long long ai0 = 0ull, af0 = 0ull, ag0 = 0ull, ao0 = 0ull;
        unsigned long long ai1 = 0ull, af1 = 0ull, ag1 = 0ull, ao1 = 0ull;
#pragma unroll 4
        for (int k4 = 0; k4 < 128; k4++) {
            ulonglong2 h0 = Hr0[k4];
            ulonglong2 h1 = Hr1[k4];
            ulonglong2 wi = Wi[k4];
            ulonglong2 wf = Wf[k4];
            ulonglong2 wg = Wg[k4];
            ulonglong2 wo = Wo[k4];
            ffma2(ai0, h0.x, wi.x); ffma2(ai0, h0.y, wi.y);
            ffma2(ai1, h1.x, wi.x); ffma2(ai1, h1.y, wi.y);
            ffma2(af0, h0.x, wf.x); ffma2(af0, h0.y, wf.y);
            ffma2(af1, h1.x, wf.x); ffma2(af1, h1.y, wf.y);
            ffma2(ag0, h0.x, wg.x); ffma2(ag0, h0.y, wg.y);
            ffma2(ag1, h1.x, wg.x); ffma2(ag1, h1.y, wg.y);
            ffma2(ao0, h0.x, wo.x); ffma2(ao0, h0.y, wo.y);
            ffma2(ao1, h1.x, wo.x); ffma2(ao1, h1.y, wo.y);
        }

        float gi0 = sigmoidf_(xi0  + pairsum(ai0));
        float gf0 = sigmoidf_(xf0  + pairsum(af0));
        float gg0 = tanhf    (xg0g + pairsum(ag0));
        float go0 = sigmoidf_(xo0  + pairsum(ao0));
        float gi1 = sigmoidf_(xi1  + pairsum(ai1));
        float gf1 = sigmoidf_(xf1  + pairsum(af1));
        float gg1 = tanhf    (xg1g + pairsum(ag1));
        float go1 = sigmoidf_(xo1  + pairsum(ao1));
        c0 = gf0 * c0 + gi0 * gg0;
        c1 = gf1 * c1 + gi1 * gg1;
        float h0v = go0 * tanhf(c0);
        float h1v = go1 * tanhf(c1);
        __stcg(&g_h[(t + 1) & 1][b0 * HH + j], h0v);
        __stcg(&g_h[(t + 1) & 1][b1 * HH + j], h1v);

        // ---- group barrier (arrive early; g_hs stores ride the poll) ----
        __threadfence();
        __syncthreads();
        if (tid == 0) {
            unsigned int my = *((volatile unsigned int*)&g_bars[bg].gen);
            unsigned int arrived = atomicAdd(&g_bars[bg].count, 1u);
            if (arrived == 31u) {
                atomicExch(&g_bars[bg].count, 0u);
                __threadfence();
                atomicAdd(&g_bars[bg].gen, 1u);
            }
            // history stores (no inter-CTA consumer; only fc_gemm after end)
            g_hs[((size_t)t * BB + b0) * HH + j] = h0v;
            g_hs[((size_t)t * BB + b1) * HH + j] = h1v;
            if (arrived != 31u) {
                while (*((volatile unsigned int*)&g_bars[bg].gen) == my) { __nanosleep(32); }
            }
            __threadfence();
        } else {
            g_hs[((size_t)t * BB + b0) * HH + j] = h0v;
            g_hs[((size_t)t * BB + b1) * HH + j] = h1v;
        }
        __syncthreads();
    }
}

// ---------------------------------------------------------------------------
// Phase 3: out[b][t][c] = hs[t][b][:] . W_fc[c][:] + b_fc[c]  (unchanged)
// ---------------------------------------------------------------------------
__global__ void __launch_bounds__(256) fc_gemm(
    const float* __restrict__ W_fc,
    const float* __restrict__ b_fc,
    float* __restrict__ out)
{
    __shared__ float As[8][128];
    __shared__ float Bs[8][128];

    const int m0 = blockIdx.x * 128;
    const int tid = threadIdx.x;
    const int tx = tid & 15;
    const int ty = tid >> 4;

    float acc[8][8];
#pragma unroll
    for (int i = 0; i < 8; i++)
#pragma unroll
        for (int j = 0; j < 8; j++) acc[i][j] = 0.0f;

    const int lr = tid >> 1;
    const int lk = (tid & 1) * 4;

    for (int k0 = 0; k0 < HH; k0 += 8) {
        {
            float4 v = *(const float4*)(g_hs + (size_t)(m0 + lr) * HH + k0 + lk);
            As[lk + 0][lr] = v.x; As[lk + 1][lr] = v.y;
            As[lk + 2][lr] = v.z; As[lk + 3][lr] = v.w;
        }
        {
            float4 v = *(const float4*)(W_fc + (size_t)lr * HH + k0 + lk);
            Bs[lk + 0][lr] = v.x; Bs[lk + 1][lr] = v.y;
            Bs[lk + 2][lr] = v.z; Bs[lk + 3][lr] = v.w;
        }
        __syncthreads();
#pragma unroll
        for (int k = 0; k < 8; k++) {
            float a[8], b[8];
            float4 a0 = *(const float4*)&As[k][ty * 4];
            float4 a1 = *(const float4*)&As[k][64 + ty * 4];
            float4 b0 = *(const float4*)&Bs[k][tx * 4];
            float4 b1 = *(const float4*)&Bs[k][64 + tx * 4];
            a[0]=a0.x; a[1]=a0.y; a[2]=a0.z; a[3]=a0.w;
            a[4]=a1.x; a[5]=a1.y; a[6]=a1.z; a[7]=a1.w;
            b[0]=b0.x; b[1]=b0.y; b[2]=b0.z; b[3]=b0.w;
            b[4]=b1.x; b[5]=b1.y; b[6]=b1.z; b[7]=b1.w;
#pragma unroll
            for (int i = 0; i < 8; i++)
#pragma unroll
                for (int j = 0; j < 8; j++)
                    acc[i][j] = fmaf(a[i], b[j], acc[i][j]);
        }
        __syncthreads();
    }

#pragma unroll
    for (int i = 0; i < 8; i++) {
        int m = m0 + (i >> 2) * 64 + ty * 4 + (i & 3);
        int bb = m & 63;
        int tt = m >> 6;
        size_t orow = ((size_t)bb * TT + tt) * CC;
#pragma unroll
        for (int j = 0; j < 8; j++) {
            int cc = (j >> 2) * 64 + tx * 4 + (j & 3);
            out[orow + cc] = acc[i][j] + b_fc[cc];
        }
    }
}

// ---------------------------------------------------------------------------
extern "C" void kernel_launch(void* const* d_in, const int* in_sizes, int n_in,
                              void* d_out, int out_size)
{
    const float* x    = (const float*)d_in[0];
    const float* W_ih = (const float*)d_in[1];
    const float* W_hh = (const float*)d_in[2];
    const float* b_ih = (const float*)d_in[3];
    const float* b_hh = (const float*)d_in[4];
    const float* W_fc = (const float*)d_in[5];
    const float* b_fc = (const float*)d_in[6];
    float* out = (float*)d_out;

    cudaFuncSetAttribute(lstm_recur,
                         cudaFuncAttributeMaxDynamicSharedMemorySize,
                         SMEM_RECUR);

    dim3 g1(4 * HH / 128, (BB * TT) / 128);   // (16, 256)
    gates_gemm<<<g1, 256>>>(x, W_ih, b_ih, b_hh);

    lstm_recur<<<128, 128, SMEM_RECUR>>>(W_hh);   // 128 CTAs, co-resident

    fc_gemm<<<(BB * TT) / 128, 256>>>(W_fc, b_fc, out);
}